// round 12
// baseline (speedup 1.0000x reference)
#include <cuda_runtime.h>

// TAHE: masked cosine-similarity weighted pooling.
// out[b,d] = sum_l [ts[b,l]>0] * (dot(cur_n[b], rec_n[b,l]) + 1)/2 * emb[b,l,d]
//
// R12: warp-granular dynamic work stealing.
//   - one warp processes one full batch row (L=200): weights phase (rec,
//     pipelined) then pooling phase (emb stream). No cross-warp combine,
//     no __syncthreads in the work path.
//   - warps pull batch indices from a global atomic ticket counter, so
//     slow warps take fewer tickets and all finish together -> removes the
//     end-of-kernel DRAM-idle tail (dram busy was only 70%).
//   - counter reset by a tiny kernel launched first (graph-capturable).

#define TAHE_B 4096
#define TAHE_L 200
#define TAHE_D 128
#define WARPS_PER_CTA 8
#define NUM_CTAS 296            // 2 CTAs/SM waves-worth; stealing balances

__device__ int g_ticket;

__global__ void tahe_reset_kernel() { g_ticket = 0; }

__global__ __launch_bounds__(WARPS_PER_CTA * 32, 8)
void tahe_kernel(const float* __restrict__ rec,
                 const float* __restrict__ cur,
                 const int*   __restrict__ ts,
                 const float* __restrict__ emb,
                 float*       __restrict__ out) {
    __shared__ short s_list[WARPS_PER_CTA][TAHE_L + 8];
    __shared__ float s_w   [WARPS_PER_CTA][TAHE_L + 8];

    const int warp = threadIdx.x >> 5;
    const int lane = threadIdx.x & 31;
    const unsigned lanemask_lt = (1u << lane) - 1u;

    for (;;) {
        // ---- pull next batch row from the global ticket counter ----
        int b;
        if (lane == 0) b = atomicAdd(&g_ticket, 1);
        b = __shfl_sync(0xFFFFFFFFu, b, 0);
        if (b >= TAHE_B) break;

        // ---- normalize current representation ----
        float4 c = reinterpret_cast<const float4*>(cur + (size_t)b * TAHE_D)[lane];
        float csq = c.x * c.x + c.y * c.y + c.z * c.z + c.w * c.w;
        #pragma unroll
        for (int o = 16; o > 0; o >>= 1)
            csq += __shfl_xor_sync(0xFFFFFFFFu, csq, o);
        const float cinv = rsqrtf(fmaxf(csq, 1e-12f));
        c.x *= cinv; c.y *= cinv; c.z *= cinv; c.w *= cinv;

        // ---- compact active l indices (L=200 -> 7 ballot chunks) ----
        const int* tsb = ts + (size_t)b * TAHE_L;
        int cnt = 0;
        #pragma unroll
        for (int chunk = 0; chunk < 7; chunk++) {      // 7*32 = 224 >= 200
            const int li = chunk * 32 + lane;
            const int t  = (li < TAHE_L) ? tsb[li] : 0;
            const unsigned ballot = __ballot_sync(0xFFFFFFFFu, t > 0);
            if (t > 0)
                s_list[warp][cnt + __popc(ballot & lanemask_lt)] = (short)li;
            cnt += __popc(ballot);
        }
        __syncwarp();

        const float4* recb = reinterpret_cast<const float4*>(rec + (size_t)b * TAHE_L * TAHE_D);
        const float4* embb = reinterpret_cast<const float4*>(emb + (size_t)b * TAHE_L * TAHE_D);

        // ============ Phase 1: weights (rec only, pipelined) ============
        {
            int i = 0;
            if (cnt >= 2) {
                float4 ra = __ldcs(&recb[(size_t)s_list[warp][0] * 32 + lane]);
                float4 rb = __ldcs(&recb[(size_t)s_list[warp][1] * 32 + lane]);

                for (;;) {
                    float d0 = ra.x*c.x + ra.y*c.y + ra.z*c.z + ra.w*c.w;
                    float s0 = ra.x*ra.x + ra.y*ra.y + ra.z*ra.z + ra.w*ra.w;
                    float d1 = rb.x*c.x + rb.y*c.y + rb.z*c.z + rb.w*c.w;
                    float s1 = rb.x*rb.x + rb.y*rb.y + rb.z*rb.z + rb.w*rb.w;

                    // prefetch next pair while the shuffle chain runs
                    const int ii = i + 2;
                    const bool more = (ii + 2 <= cnt);
                    const int n0 = more ? (int)s_list[warp][ii]     : 0;
                    const int n1 = more ? (int)s_list[warp][ii + 1] : 0;
                    ra = __ldcs(&recb[(size_t)n0 * 32 + lane]);
                    rb = __ldcs(&recb[(size_t)n1 * 32 + lane]);

                    #pragma unroll
                    for (int o = 16; o > 0; o >>= 1) {
                        d0 += __shfl_xor_sync(0xFFFFFFFFu, d0, o);
                        s0 += __shfl_xor_sync(0xFFFFFFFFu, s0, o);
                        d1 += __shfl_xor_sync(0xFFFFFFFFu, d1, o);
                        s1 += __shfl_xor_sync(0xFFFFFFFFu, s1, o);
                    }

                    if (lane == 0) {
                        s_w[warp][i]     = (d0 * rsqrtf(fmaxf(s0, 1e-12f)) + 1.0f) * 0.5f;
                        s_w[warp][i + 1] = (d1 * rsqrtf(fmaxf(s1, 1e-12f)) + 1.0f) * 0.5f;
                    }

                    i = ii;
                    if (!more) break;
                }
            }
            if (cnt & 1) {
                const float4 r0 = __ldcs(&recb[(size_t)s_list[warp][cnt - 1] * 32 + lane]);
                float d0 = r0.x*c.x + r0.y*c.y + r0.z*c.z + r0.w*c.w;
                float s0 = r0.x*r0.x + r0.y*r0.y + r0.z*r0.z + r0.w*r0.w;
                #pragma unroll
                for (int o = 16; o > 0; o >>= 1) {
                    d0 += __shfl_xor_sync(0xFFFFFFFFu, d0, o);
                    s0 += __shfl_xor_sync(0xFFFFFFFFu, s0, o);
                }
                if (lane == 0)
                    s_w[warp][cnt - 1] = (d0 * rsqrtf(fmaxf(s0, 1e-12f)) + 1.0f) * 0.5f;
            }
        }
        __syncwarp();

        // ============ Phase 2: pooling (emb only, pure stream) ============
        float4 accA = make_float4(0.f, 0.f, 0.f, 0.f);
        float4 accB = make_float4(0.f, 0.f, 0.f, 0.f);

        int i = 0;
        for (; i + 4 <= cnt; i += 4) {
            const int l0 = s_list[warp][i];
            const int l1 = s_list[warp][i + 1];
            const int l2 = s_list[warp][i + 2];
            const int l3 = s_list[warp][i + 3];
            const float w0 = s_w[warp][i];
            const float w1 = s_w[warp][i + 1];
            const float w2 = s_w[warp][i + 2];
            const float w3 = s_w[warp][i + 3];

            const float4 e0 = __ldcs(&embb[(size_t)l0 * 32 + lane]);
            const float4 e1 = __ldcs(&embb[(size_t)l1 * 32 + lane]);
            const float4 e2 = __ldcs(&embb[(size_t)l2 * 32 + lane]);
            const float4 e3 = __ldcs(&embb[(size_t)l3 * 32 + lane]);

            accA.x = fmaf(w0, e0.x, fmaf(w1, e1.x, accA.x));
            accA.y = fmaf(w0, e0.y, fmaf(w1, e1.y, accA.y));
            accA.z = fmaf(w0, e0.z, fmaf(w1, e1.z, accA.z));
            accA.w = fmaf(w0, e0.w, fmaf(w1, e1.w, accA.w));
            accB.x = fmaf(w2, e2.x, fmaf(w3, e3.x, accB.x));
            accB.y = fmaf(w2, e2.y, fmaf(w3, e3.y, accB.y));
            accB.z = fmaf(w2, e2.z, fmaf(w3, e3.z, accB.z));
            accB.w = fmaf(w2, e2.w, fmaf(w3, e3.w, accB.w));
        }
        for (; i < cnt; i++) {
            const int l0 = s_list[warp][i];
            const float w0 = s_w[warp][i];
            const float4 e0 = __ldcs(&embb[(size_t)l0 * 32 + lane]);
            accA.x = fmaf(w0, e0.x, accA.x);
            accA.y = fmaf(w0, e0.y, accA.y);
            accA.z = fmaf(w0, e0.z, accA.z);
            accA.w = fmaf(w0, e0.w, accA.w);
        }

        float4 acc = make_float4(accA.x + accB.x, accA.y + accB.y,
                                 accA.z + accB.z, accA.w + accB.w);
        reinterpret_cast<float4*>(out + (size_t)b * TAHE_D)[lane] = acc;
    }
}

extern "C" void kernel_launch(void* const* d_in, const int* in_sizes, int n_in,
                              void* d_out, int out_size) {
    const float* rec = (const float*)d_in[0];
    const float* cur = (const float*)d_in[1];
    const int*   ts  = (const int*)  d_in[2];
    const float* emb = (const float*)d_in[3];
    float*       out = (float*)d_out;

    tahe_reset_kernel<<<1, 1>>>();
    tahe_kernel<<<NUM_CTAS, WARPS_PER_CTA * 32>>>(rec, cur, ts, emb, out);
}

// round 13
// speedup vs baseline: 1.7384x; 1.7384x over previous
#include <cuda_runtime.h>

// TAHE: masked cosine-similarity weighted pooling.
// out[b,d] = sum_l [ts[b,l]>0] * (dot(cur_n[b], rec_n[b,l]) + 1)/2 * emb[b,l,d]
//
// R13: 1 batch row per 128-thread CTA (4 warps x L/4 = 50 each), grid=4096.
//   Residency ~16 CTAs/SM -> 1.73 waves: the HW CTA scheduler dynamically
//   backfills finished slots, absorbing per-warp cnt/queue skew that left
//   DRAM idle ~30% in single-wave R10 (and without R12's atomic/occupancy
//   mistakes). Proven two-phase body: pipelined rec weights, pure emb stream.

#define TAHE_B 4096
#define TAHE_L 200
#define TAHE_D 128
#define WARPS_PER_CTA 4
#define L_QTR 50               // L per warp

__global__ __launch_bounds__(WARPS_PER_CTA * 32, 16)
void tahe_kernel(const float* __restrict__ rec,
                 const float* __restrict__ cur,
                 const int*   __restrict__ ts,
                 const float* __restrict__ emb,
                 float*       __restrict__ out) {
    __shared__ short s_list[WARPS_PER_CTA][L_QTR + 6];
    __shared__ float s_w   [WARPS_PER_CTA][L_QTR + 6];
    __shared__ float s_part[WARPS_PER_CTA][TAHE_D];

    const int warp = threadIdx.x >> 5;
    const int lane = threadIdx.x & 31;
    const int b    = blockIdx.x;

    const unsigned lanemask_lt = (1u << lane) - 1u;

    // ---- normalize current representation (lane owns 4 contiguous floats) ----
    float4 c = reinterpret_cast<const float4*>(cur + (size_t)b * TAHE_D)[lane];
    float csq = c.x * c.x + c.y * c.y + c.z * c.z + c.w * c.w;
    #pragma unroll
    for (int o = 16; o > 0; o >>= 1)
        csq += __shfl_xor_sync(0xFFFFFFFFu, csq, o);
    const float cinv = rsqrtf(fmaxf(csq, 1e-12f));
    c.x *= cinv; c.y *= cinv; c.z *= cinv; c.w *= cinv;

    // ---- compact active l indices for this warp's L-quarter into smem ----
    const int* tsb = ts + (size_t)b * TAHE_L + warp * L_QTR;
    int cnt = 0;
    #pragma unroll
    for (int chunk = 0; chunk < 2; chunk++) {           // 2*32 = 64 >= 50
        const int li = chunk * 32 + lane;
        const int t  = (li < L_QTR) ? tsb[li] : 0;
        const unsigned ballot = __ballot_sync(0xFFFFFFFFu, t > 0);
        if (t > 0)
            s_list[warp][cnt + __popc(ballot & lanemask_lt)] =
                (short)(warp * L_QTR + li);
        cnt += __popc(ballot);
    }
    __syncwarp();

    const float4* recb = reinterpret_cast<const float4*>(rec + (size_t)b * TAHE_L * TAHE_D);
    const float4* embb = reinterpret_cast<const float4*>(emb + (size_t)b * TAHE_L * TAHE_D);

    // ================= Phase 1: weights (rec only, pipelined) =================
    {
        int i = 0;
        if (cnt >= 2) {
            float4 ra = __ldcs(&recb[(size_t)s_list[warp][0] * 32 + lane]);
            float4 rb = __ldcs(&recb[(size_t)s_list[warp][1] * 32 + lane]);

            for (;;) {
                float d0 = ra.x*c.x + ra.y*c.y + ra.z*c.z + ra.w*c.w;
                float s0 = ra.x*ra.x + ra.y*ra.y + ra.z*ra.z + ra.w*ra.w;
                float d1 = rb.x*c.x + rb.y*c.y + rb.z*c.z + rb.w*c.w;
                float s1 = rb.x*rb.x + rb.y*rb.y + rb.z*rb.z + rb.w*rb.w;

                // prefetch next pair while the shuffle chain runs
                const int ii = i + 2;
                const bool more = (ii + 2 <= cnt);
                const int n0 = more ? (int)s_list[warp][ii]     : 0;
                const int n1 = more ? (int)s_list[warp][ii + 1] : 0;
                ra = __ldcs(&recb[(size_t)n0 * 32 + lane]);
                rb = __ldcs(&recb[(size_t)n1 * 32 + lane]);

                #pragma unroll
                for (int o = 16; o > 0; o >>= 1) {
                    d0 += __shfl_xor_sync(0xFFFFFFFFu, d0, o);
                    s0 += __shfl_xor_sync(0xFFFFFFFFu, s0, o);
                    d1 += __shfl_xor_sync(0xFFFFFFFFu, d1, o);
                    s1 += __shfl_xor_sync(0xFFFFFFFFu, s1, o);
                }

                if (lane == 0) {
                    s_w[warp][i]     = (d0 * rsqrtf(fmaxf(s0, 1e-12f)) + 1.0f) * 0.5f;
                    s_w[warp][i + 1] = (d1 * rsqrtf(fmaxf(s1, 1e-12f)) + 1.0f) * 0.5f;
                }

                i = ii;
                if (!more) break;
            }
        }
        if (cnt & 1) {
            const float4 r0 = __ldcs(&recb[(size_t)s_list[warp][cnt - 1] * 32 + lane]);
            float d0 = r0.x*c.x + r0.y*c.y + r0.z*c.z + r0.w*c.w;
            float s0 = r0.x*r0.x + r0.y*r0.y + r0.z*r0.z + r0.w*r0.w;
            #pragma unroll
            for (int o = 16; o > 0; o >>= 1) {
                d0 += __shfl_xor_sync(0xFFFFFFFFu, d0, o);
                s0 += __shfl_xor_sync(0xFFFFFFFFu, s0, o);
            }
            if (lane == 0)
                s_w[warp][cnt - 1] = (d0 * rsqrtf(fmaxf(s0, 1e-12f)) + 1.0f) * 0.5f;
        }
    }
    __syncwarp();

    // ================= Phase 2: pooling (emb only, pure stream) ===============
    float4 accA = make_float4(0.f, 0.f, 0.f, 0.f);
    float4 accB = make_float4(0.f, 0.f, 0.f, 0.f);

    int i = 0;
    for (; i + 4 <= cnt; i += 4) {
        const int l0 = s_list[warp][i];
        const int l1 = s_list[warp][i + 1];
        const int l2 = s_list[warp][i + 2];
        const int l3 = s_list[warp][i + 3];
        const float w0 = s_w[warp][i];
        const float w1 = s_w[warp][i + 1];
        const float w2 = s_w[warp][i + 2];
        const float w3 = s_w[warp][i + 3];

        const float4 e0 = __ldcs(&embb[(size_t)l0 * 32 + lane]);
        const float4 e1 = __ldcs(&embb[(size_t)l1 * 32 + lane]);
        const float4 e2 = __ldcs(&embb[(size_t)l2 * 32 + lane]);
        const float4 e3 = __ldcs(&embb[(size_t)l3 * 32 + lane]);

        accA.x = fmaf(w0, e0.x, fmaf(w1, e1.x, accA.x));
        accA.y = fmaf(w0, e0.y, fmaf(w1, e1.y, accA.y));
        accA.z = fmaf(w0, e0.z, fmaf(w1, e1.z, accA.z));
        accA.w = fmaf(w0, e0.w, fmaf(w1, e1.w, accA.w));
        accB.x = fmaf(w2, e2.x, fmaf(w3, e3.x, accB.x));
        accB.y = fmaf(w2, e2.y, fmaf(w3, e3.y, accB.y));
        accB.z = fmaf(w2, e2.z, fmaf(w3, e3.z, accB.z));
        accB.w = fmaf(w2, e2.w, fmaf(w3, e3.w, accB.w));
    }
    for (; i < cnt; i++) {
        const int l0 = s_list[warp][i];
        const float w0 = s_w[warp][i];
        const float4 e0 = __ldcs(&embb[(size_t)l0 * 32 + lane]);
        accA.x = fmaf(w0, e0.x, accA.x);
        accA.y = fmaf(w0, e0.y, accA.y);
        accA.z = fmaf(w0, e0.z, accA.z);
        accA.w = fmaf(w0, e0.w, accA.w);
    }
    const float4 acc = make_float4(accA.x + accB.x, accA.y + accB.y,
                                   accA.z + accB.z, accA.w + accB.w);

    // ---- combine the four quarter-warps (fixed order -> deterministic) ----
    reinterpret_cast<float4*>(s_part[warp])[lane] = acc;
    __syncthreads();

    const int t = threadIdx.x;           // 0..127 -> one output element each
    const float v = s_part[0][t] + s_part[1][t] + s_part[2][t] + s_part[3][t];
    out[(size_t)b * TAHE_D + t] = v;
}

extern "C" void kernel_launch(void* const* d_in, const int* in_sizes, int n_in,
                              void* d_out, int out_size) {
    const float* rec = (const float*)d_in[0];
    const float* cur = (const float*)d_in[1];
    const int*   ts  = (const int*)  d_in[2];
    const float* emb = (const float*)d_in[3];
    float*       out = (float*)d_out;

    tahe_kernel<<<TAHE_B, WARPS_PER_CTA * 32>>>(rec, cur, ts, emb, out);
}